// round 5
// baseline (speedup 1.0000x reference)
#include <cuda_runtime.h>
#include <math.h>

#define BSZ 2048
#define ESZ 512
#define CSZ 16384
#define NBLK (CSZ / 128)   // 128 column-blocks of the logits GEMM

// ---------------- scratch (static device globals; no allocation) ----------------
__device__ float g_sim[(size_t)BSZ * BSZ];      // 16 MiB
__device__ float g_tsim[(size_t)BSZ * BSZ];     // 16 MiB
__device__ float g_pmax[(size_t)BSZ * NBLK];    // 1 MiB  per-(row,colblock) max
__device__ float g_psum[(size_t)BSZ * NBLK];    // 1 MiB  per-(row,colblock) sumexp
__device__ float g_rowlabel[BSZ];               // logits[b][label[b]]
__device__ float g_colscale[CSZ];
__device__ float g_rowrank[BSZ];
__device__ float g_rowkd[BSZ];
__device__ int   g_lab64;

// Detect labels dtype: int64 little-endian with values <256 -> all odd int32
// words are zero (1024 of them). int32 labels -> odd words hold real labels.
__global__ void detect_labels_kernel(const int* __restrict__ labels) {
    __shared__ int cnt[256];
    int t = threadIdx.x;
    int c = 0;
    for (int i = t; i < BSZ; i += 256)
        if ((i & 1) && labels[i] != 0) c++;
    cnt[t] = c;
    __syncthreads();
    for (int o = 128; o; o >>= 1) {
        if (t < o) cnt[t] += cnt[t + o];
        __syncthreads();
    }
    if (t == 0) g_lab64 = (cnt[0] == 0) ? 1 : 0;
}

__device__ __forceinline__ int get_label(const int* __restrict__ labels, int b) {
    return g_lab64 ? labels[2 * b] : labels[b];
}

// per-class scale: rsqrt(||row||^2) / TEMPERATURE  (one warp per class row)
__global__ void colscale_kernel(const float* __restrict__ cm) {
    int c = blockIdx.x * 8 + (threadIdx.x >> 5);
    int lane = threadIdx.x & 31;
    const float4* row = (const float4*)(cm + (size_t)c * ESZ);
    float s = 0.f;
    #pragma unroll 4
    for (int i = lane; i < ESZ / 4; i += 32) {
        float4 v = row[i];
        s += v.x * v.x + v.y * v.y + v.z * v.z + v.w * v.w;
    }
    #pragma unroll
    for (int o = 16; o; o >>= 1) s += __shfl_xor_sync(0xffffffffu, s, o);
    if (lane == 0) g_colscale[c] = rsqrtf(s) * 20.0f;  // 1/TEMPERATURE
}

// fp32 SIMT NT GEMM: C[m,n] = sum_k A[m,k]*B[n,k].
// dest==0: logits path — scale by g_colscale[n], do NOT store the tile;
//          instead emit per-row (max, sumexp) partials + the label-column value.
// dest==1/2: store to g_sim / g_tsim.
// BM=BN=128, BK=16, 256 threads, 8x8 microtile.
__global__ void __launch_bounds__(256) gemm_nt_kernel(
    const float* __restrict__ A, const float* __restrict__ Bm,
    int K, int N, int dest, const int* __restrict__ labels)
{
    __shared__ alignas(16) float As[16][132];
    __shared__ alignas(16) float Bs[16][132];

    int bm = blockIdx.y * 128;
    int bn = blockIdx.x * 128;
    int tid = threadIdx.x;
    int tr = tid >> 4;
    int tc = tid & 15;

    float acc[8][8];
    #pragma unroll
    for (int i = 0; i < 8; i++)
        #pragma unroll
        for (int j = 0; j < 8; j++) acc[i][j] = 0.f;

    const float* Abase = A + (size_t)bm * K;
    const float* Bbase = Bm + (size_t)bn * K;

    int row0 = tid >> 2,         kq0 = tid & 3;
    int row1 = (tid + 256) >> 2, kq1 = tid & 3;

    for (int kt = 0; kt < K; kt += 16) {
        float4 av0 = *(const float4*)(Abase + (size_t)row0 * K + kt + kq0 * 4);
        float4 bv0 = *(const float4*)(Bbase + (size_t)row0 * K + kt + kq0 * 4);
        float4 av1 = *(const float4*)(Abase + (size_t)row1 * K + kt + kq1 * 4);
        float4 bv1 = *(const float4*)(Bbase + (size_t)row1 * K + kt + kq1 * 4);
        As[kq0 * 4 + 0][row0] = av0.x; As[kq0 * 4 + 1][row0] = av0.y;
        As[kq0 * 4 + 2][row0] = av0.z; As[kq0 * 4 + 3][row0] = av0.w;
        Bs[kq0 * 4 + 0][row0] = bv0.x; Bs[kq0 * 4 + 1][row0] = bv0.y;
        Bs[kq0 * 4 + 2][row0] = bv0.z; Bs[kq0 * 4 + 3][row0] = bv0.w;
        As[kq1 * 4 + 0][row1] = av1.x; As[kq1 * 4 + 1][row1] = av1.y;
        As[kq1 * 4 + 2][row1] = av1.z; As[kq1 * 4 + 3][row1] = av1.w;
        Bs[kq1 * 4 + 0][row1] = bv1.x; Bs[kq1 * 4 + 1][row1] = bv1.y;
        Bs[kq1 * 4 + 2][row1] = bv1.z; Bs[kq1 * 4 + 3][row1] = bv1.w;
        __syncthreads();
        #pragma unroll
        for (int kk = 0; kk < 16; kk++) {
            float a[8], b[8];
            *(float4*)(a)     = *(const float4*)&As[kk][tr * 8];
            *(float4*)(a + 4) = *(const float4*)&As[kk][tr * 8 + 4];
            *(float4*)(b)     = *(const float4*)&Bs[kk][tc * 8];
            *(float4*)(b + 4) = *(const float4*)&Bs[kk][tc * 8 + 4];
            #pragma unroll
            for (int i = 0; i < 8; i++)
                #pragma unroll
                for (int j = 0; j < 8; j++)
                    acc[i][j] += a[i] * b[j];
        }
        __syncthreads();
    }

    if (dest == 0) {
        // Fused loss_rank partial reduction. Scale columns, then per-row
        // online-softmax partials across this block's 128 columns.
        float sc[8];
        #pragma unroll
        for (int j = 0; j < 8; j++) sc[j] = g_colscale[bn + tc * 8 + j];

        #pragma unroll
        for (int i = 0; i < 8; i++) {
            int r = bm + tr * 8 + i;
            int lab = get_label(labels, r);
            float m = -1e30f;
            float v[8];
            #pragma unroll
            for (int j = 0; j < 8; j++) {
                v[j] = acc[i][j] * sc[j];
                if (bn + tc * 8 + j == lab) g_rowlabel[r] = v[j];
                m = fmaxf(m, v[j]);
            }
            float s = 0.f;
            #pragma unroll
            for (int j = 0; j < 8; j++) s += __expf(v[j] - m);
            // reduce (m,s) across the 16 lanes sharing tr (contiguous half-warp)
            #pragma unroll
            for (int o = 8; o; o >>= 1) {
                float m2 = __shfl_xor_sync(0xffffffffu, m, o);
                float s2 = __shfl_xor_sync(0xffffffffu, s, o);
                float M = fmaxf(m, m2);
                s = s * __expf(m - M) + s2 * __expf(m2 - M);
                m = M;
            }
            if (tc == 0) {
                g_pmax[(size_t)r * NBLK + blockIdx.x] = m;
                g_psum[(size_t)r * NBLK + blockIdx.x] = s;
            }
        }
    } else {
        float* Cg = (dest == 1) ? g_sim : g_tsim;
        #pragma unroll
        for (int i = 0; i < 8; i++) {
            float* crow = Cg + (size_t)(bm + tr * 8 + i) * N + bn + tc * 8;
            float4 v0, v1;
            v0.x = acc[i][0]; v0.y = acc[i][1]; v0.z = acc[i][2]; v0.w = acc[i][3];
            v1.x = acc[i][4]; v1.y = acc[i][5]; v1.z = acc[i][6]; v1.w = acc[i][7];
            ((float4*)crow)[0] = v0;
            ((float4*)crow)[1] = v1;
        }
    }
}

// merge the NBLK logsumexp partials per row; subtract the label logit
__global__ void rank_merge_kernel() {
    int b = blockIdx.x;
    int t = threadIdx.x;  // 128 threads, one per column-block partial
    __shared__ float sm[128], ss[128];
    sm[t] = g_pmax[(size_t)b * NBLK + t];
    ss[t] = g_psum[(size_t)b * NBLK + t];
    __syncthreads();
    for (int o = 64; o; o >>= 1) {
        if (t < o) {
            float m2 = sm[t + o], s2 = ss[t + o];
            float M = fmaxf(sm[t], m2);
            ss[t] = ss[t] * __expf(sm[t] - M) + s2 * __expf(m2 - M);
            sm[t] = M;
        }
        __syncthreads();
    }
    if (t == 0) g_rowrank[b] = sm[0] + logf(ss[0]) - g_rowlabel[b];
}

// per-row KD: scale = (same label ? 1 : 0.5)/TAU, softmax for s and t, KL sum
__global__ void kd_kernel(const int* __restrict__ labels) {
    int b = blockIdx.x;
    int t = threadIdx.x;
    __shared__ float zs[BSZ];
    __shared__ float zt[BSZ];
    __shared__ float red[256];

    int lb = get_label(labels, b);
    const float* srow = g_sim  + (size_t)b * BSZ;
    const float* trow = g_tsim + (size_t)b * BSZ;

    float ms = -1e30f, mt = -1e30f;
    for (int j = t; j < BSZ; j += 256) {
        float sc = (get_label(labels, j) == lb) ? 0.25f : 0.125f;  // 1/TAU, BETA/TAU
        float a = srow[j] * sc;
        float c = trow[j] * sc;
        zs[j] = a; zt[j] = c;
        ms = fmaxf(ms, a);
        mt = fmaxf(mt, c);
    }
    __syncthreads();

    red[t] = ms; __syncthreads();
    for (int o = 128; o; o >>= 1) { if (t < o) red[t] = fmaxf(red[t], red[t + o]); __syncthreads(); }
    ms = red[0]; __syncthreads();

    red[t] = mt; __syncthreads();
    for (int o = 128; o; o >>= 1) { if (t < o) red[t] = fmaxf(red[t], red[t + o]); __syncthreads(); }
    mt = red[0]; __syncthreads();

    float sums = 0.f, sumt = 0.f;
    for (int j = t; j < BSZ; j += 256) {
        sums += __expf(zs[j] - ms);
        sumt += __expf(zt[j] - mt);
    }
    red[t] = sums; __syncthreads();
    for (int o = 128; o; o >>= 1) { if (t < o) red[t] += red[t + o]; __syncthreads(); }
    sums = red[0]; __syncthreads();

    red[t] = sumt; __syncthreads();
    for (int o = 128; o; o >>= 1) { if (t < o) red[t] += red[t + o]; __syncthreads(); }
    sumt = red[0]; __syncthreads();

    float lss = logf(sums);
    float lst = logf(sumt);
    float kl = 0.f;
    for (int j = t; j < BSZ; j += 256) {
        float tl = zt[j] - mt - lst;
        float sl = zs[j] - ms - lss;
        kl += __expf(tl) * (tl - sl);
    }
    red[t] = kl; __syncthreads();
    for (int o = 128; o; o >>= 1) { if (t < o) red[t] += red[t + o]; __syncthreads(); }
    if (t == 0) g_rowkd[b] = red[0];
}

__global__ void final_kernel(const int* __restrict__ epoch_ptr, float* __restrict__ out,
                             int out_size) {
    __shared__ float r1[256], r2[256];
    int t = threadIdx.x;
    float a = 0.f, c = 0.f;
    for (int i = t; i < BSZ; i += 256) { a += g_rowrank[i]; c += g_rowkd[i]; }
    r1[t] = a; r2[t] = c;
    __syncthreads();
    for (int o = 128; o; o >>= 1) {
        if (t < o) { r1[t] += r1[t + o]; r2[t] += r2[t + o]; }
        __syncthreads();
    }
    if (t == 0) {
        float loss_rank = r1[0] * (1.0f / BSZ);
        float loss_kd   = r2[0] * (1.0f / BSZ);
        int epoch = epoch_ptr[0];  // low word valid for int32 and int64 encodings
        float ramp = ((float)epoch / 150.0f) * 16.0f;  // (epoch/N_EPOCHS)*ALPHA*TAU^2
        float loss = loss_rank + ramp * loss_kd;
        out[0] = loss;
        if (out_size > 1) out[1] = loss_rank;
        if (out_size > 2) out[2] = loss_kd;
    }
}

extern "C" void kernel_launch(void* const* d_in, const int* in_sizes, int n_in,
                              void* d_out, int out_size) {
    const float* batch   = (const float*)d_in[0];
    const float* teacher = (const float*)d_in[1];
    const float* cm      = (const float*)d_in[2];
    const int*   labels  = (const int*)d_in[3];
    const int*   epoch   = (const int*)d_in[4];
    float* out = (float*)d_out;

    colscale_kernel<<<CSZ / 8, 256>>>(cm);
    detect_labels_kernel<<<1, 256>>>(labels);

    dim3 grid1(CSZ / 128, BSZ / 128);
    gemm_nt_kernel<<<grid1, 256>>>(batch, cm, ESZ, CSZ, 0, labels);

    dim3 grid2(BSZ / 128, BSZ / 128);
    gemm_nt_kernel<<<grid2, 256>>>(batch, batch, ESZ, BSZ, 1, labels);
    gemm_nt_kernel<<<grid2, 256>>>(teacher, teacher, ESZ, BSZ, 2, labels);

    rank_merge_kernel<<<BSZ, 128>>>();
    kd_kernel<<<BSZ, 256>>>(labels);
    final_kernel<<<1, 256>>>(epoch, out, out_size);
}

// round 7
// speedup vs baseline: 1.0173x; 1.0173x over previous
#include <cuda_runtime.h>
#include <math.h>

#define BSZ 2048
#define ESZ 512
#define CSZ 16384
#define NBLK (CSZ / 128)   // 128 column-blocks of the logits GEMM

// ---------------- scratch (static device globals; no allocation) ----------------
__device__ float g_sim[(size_t)BSZ * BSZ];      // 16 MiB
__device__ float g_tsim[(size_t)BSZ * BSZ];     // 16 MiB
__device__ float g_pmax[(size_t)BSZ * NBLK];    // per-(row,colblock) max
__device__ float g_psum[(size_t)BSZ * NBLK];    // per-(row,colblock) sumexp
__device__ float g_rowlabel[BSZ];               // logits[b][label[b]]
__device__ float g_colscale[CSZ];
__device__ float g_rowrank[BSZ];
__device__ float g_rowkd[BSZ];
__device__ int   g_lab64;

// Detect labels dtype: int64 little-endian with values <256 -> all odd int32
// words are zero. int32 labels -> odd words hold real labels.
__global__ void detect_labels_kernel(const int* __restrict__ labels) {
    __shared__ int cnt[256];
    int t = threadIdx.x;
    int c = 0;
    for (int i = t; i < BSZ; i += 256)
        if ((i & 1) && labels[i] != 0) c++;
    cnt[t] = c;
    __syncthreads();
    for (int o = 128; o; o >>= 1) {
        if (t < o) cnt[t] += cnt[t + o];
        __syncthreads();
    }
    if (t == 0) g_lab64 = (cnt[0] == 0) ? 1 : 0;
}

__device__ __forceinline__ int get_label(const int* __restrict__ labels, int b) {
    return g_lab64 ? labels[2 * b] : labels[b];
}

// per-class scale: rsqrt(||row||^2) / TEMPERATURE  (one warp per class row)
__global__ void colscale_kernel(const float* __restrict__ cm) {
    int c = blockIdx.x * 8 + (threadIdx.x >> 5);
    int lane = threadIdx.x & 31;
    const float4* row = (const float4*)(cm + (size_t)c * ESZ);
    float s = 0.f;
    #pragma unroll 4
    for (int i = lane; i < ESZ / 4; i += 32) {
        float4 v = row[i];
        s += v.x * v.x + v.y * v.y + v.z * v.z + v.w * v.w;
    }
    #pragma unroll
    for (int o = 16; o; o >>= 1) s += __shfl_xor_sync(0xffffffffu, s, o);
    if (lane == 0) g_colscale[c] = rsqrtf(s) * 20.0f;  // 1/TEMPERATURE
}

// ---------------- tf32 helpers ----------------
__device__ __forceinline__ unsigned f2tf32(float x) {
    unsigned y;
    asm("cvt.rna.tf32.f32 %0, %1;" : "=r"(y) : "f"(x));
    return y;
}

__device__ __forceinline__ void mma_tf32(float* d, const unsigned* a, const unsigned* b) {
    asm volatile(
        "mma.sync.aligned.m16n8k8.row.col.f32.tf32.tf32.f32 "
        "{%0,%1,%2,%3}, {%4,%5,%6,%7}, {%8,%9}, {%0,%1,%2,%3};\n"
        : "+f"(d[0]), "+f"(d[1]), "+f"(d[2]), "+f"(d[3])
        : "r"(a[0]), "r"(a[1]), "r"(a[2]), "r"(a[3]), "r"(b[0]), "r"(b[1]));
}

// ---------------- tf32 tensor-core NT GEMM ----------------
// C[m,n] = sum_k A[m,k]*B[n,k], A:[M,K] row-major, B:[N,K] row-major, K=512.
// BM=BN=128, BK=16, 256 threads = 8 warps (4 m x 2 n), warp tile 32x64.
// dest==0: logits path — scale by g_colscale[n], emit fused per-row
//          (max,sumexp) partials + label-column value. No C store.
// dest==1/2: store C to g_sim / g_tsim.
#define SPAD 136   // 128 + 8 pad: conflict-free STS and fragment LDS

__global__ void __launch_bounds__(256, 2) gemm_tf32_kernel(
    const float* __restrict__ A, const float* __restrict__ Bm,
    int K, int N, int dest, const int* __restrict__ labels)
{
    __shared__ unsigned As[2][16][SPAD];
    __shared__ unsigned Bs[2][16][SPAD];
    __shared__ float pm[128][2];
    __shared__ float ps[128][2];

    int tid  = threadIdx.x;
    int lane = tid & 31;
    int wid  = tid >> 5;
    int warp_m    = (wid >> 1) * 32;
    int wn_idx    = wid & 1;
    int warp_n    = wn_idx * 64;
    int lr = lane >> 2;   // 0..7
    int lc = lane & 3;    // 0..3

    int bm = blockIdx.y * 128;
    int bn = blockIdx.x * 128;

    // global load mapping: row = tid&127 (32 consecutive per warp), half = tid>>7
    int grow = tid & 127;
    int ghalf = tid >> 7;           // 0 or 1 -> k-offset 0 or 8
    const float* Aptr = A + (size_t)(bm + grow) * K + ghalf * 8;
    const float* Bptr = Bm + (size_t)(bn + grow) * K + ghalf * 8;

    float acc[2][8][4];
    #pragma unroll
    for (int mi = 0; mi < 2; mi++)
        #pragma unroll
        for (int ni = 0; ni < 8; ni++)
            #pragma unroll
            for (int j = 0; j < 4; j++) acc[mi][ni][j] = 0.f;

    float4 ra0, ra1, rb0, rb1;

    // prologue: tile kt=0
    ra0 = *(const float4*)(Aptr + 0);
    ra1 = *(const float4*)(Aptr + 4);
    rb0 = *(const float4*)(Bptr + 0);
    rb1 = *(const float4*)(Bptr + 4);
    {
        int kb = ghalf * 8;
        As[0][kb + 0][grow] = f2tf32(ra0.x); As[0][kb + 1][grow] = f2tf32(ra0.y);
        As[0][kb + 2][grow] = f2tf32(ra0.z); As[0][kb + 3][grow] = f2tf32(ra0.w);
        As[0][kb + 4][grow] = f2tf32(ra1.x); As[0][kb + 5][grow] = f2tf32(ra1.y);
        As[0][kb + 6][grow] = f2tf32(ra1.z); As[0][kb + 7][grow] = f2tf32(ra1.w);
        Bs[0][kb + 0][grow] = f2tf32(rb0.x); Bs[0][kb + 1][grow] = f2tf32(rb0.y);
        Bs[0][kb + 2][grow] = f2tf32(rb0.z); Bs[0][kb + 3][grow] = f2tf32(rb0.w);
        Bs[0][kb + 4][grow] = f2tf32(rb1.x); Bs[0][kb + 5][grow] = f2tf32(rb1.y);
        Bs[0][kb + 6][grow] = f2tf32(rb1.z); Bs[0][kb + 7][grow] = f2tf32(rb1.w);
    }
    __syncthreads();

    int buf = 0;
    for (int kt = 16; kt < K; kt += 16) {
        // prefetch next tile into registers
        ra0 = *(const float4*)(Aptr + kt + 0);
        ra1 = *(const float4*)(Aptr + kt + 4);
        rb0 = *(const float4*)(Bptr + kt + 0);
        rb1 = *(const float4*)(Bptr + kt + 4);

        // compute on current buffer
        #pragma unroll
        for (int ks = 0; ks < 2; ks++) {
            int k0 = ks * 8;
            unsigned af[2][4], bf[8][2];
            #pragma unroll
            for (int mi = 0; mi < 2; mi++) {
                int m0 = warp_m + mi * 16;
                af[mi][0] = As[buf][k0 + lc][m0 + lr];
                af[mi][1] = As[buf][k0 + lc][m0 + lr + 8];
                af[mi][2] = As[buf][k0 + 4 + lc][m0 + lr];
                af[mi][3] = As[buf][k0 + 4 + lc][m0 + lr + 8];
            }
            #pragma unroll
            for (int ni = 0; ni < 8; ni++) {
                int n0 = warp_n + ni * 8;
                bf[ni][0] = Bs[buf][k0 + lc][n0 + lr];
                bf[ni][1] = Bs[buf][k0 + 4 + lc][n0 + lr];
            }
            #pragma unroll
            for (int mi = 0; mi < 2; mi++)
                #pragma unroll
                for (int ni = 0; ni < 8; ni++)
                    mma_tf32(acc[mi][ni], af[mi], bf[ni]);
        }

        // store next tile into the other buffer
        int nb = buf ^ 1;
        int kb = ghalf * 8;
        As[nb][kb + 0][grow] = f2tf32(ra0.x); As[nb][kb + 1][grow] = f2tf32(ra0.y);
        As[nb][kb + 2][grow] = f2tf32(ra0.z); As[nb][kb + 3][grow] = f2tf32(ra0.w);
        As[nb][kb + 4][grow] = f2tf32(ra1.x); As[nb][kb + 5][grow] = f2tf32(ra1.y);
        As[nb][kb + 6][grow] = f2tf32(ra1.z); As[nb][kb + 7][grow] = f2tf32(ra1.w);
        Bs[nb][kb + 0][grow] = f2tf32(rb0.x); Bs[nb][kb + 1][grow] = f2tf32(rb0.y);
        Bs[nb][kb + 2][grow] = f2tf32(rb0.z); Bs[nb][kb + 3][grow] = f2tf32(rb0.w);
        Bs[nb][kb + 4][grow] = f2tf32(rb1.x); Bs[nb][kb + 5][grow] = f2tf32(rb1.y);
        Bs[nb][kb + 6][grow] = f2tf32(rb1.z); Bs[nb][kb + 7][grow] = f2tf32(rb1.w);
        __syncthreads();
        buf = nb;
    }

    // last tile
    #pragma unroll
    for (int ks = 0; ks < 2; ks++) {
        int k0 = ks * 8;
        unsigned af[2][4], bf[8][2];
        #pragma unroll
        for (int mi = 0; mi < 2; mi++) {
            int m0 = warp_m + mi * 16;
            af[mi][0] = As[buf][k0 + lc][m0 + lr];
            af[mi][1] = As[buf][k0 + lc][m0 + lr + 8];
            af[mi][2] = As[buf][k0 + 4 + lc][m0 + lr];
            af[mi][3] = As[buf][k0 + 4 + lc][m0 + lr + 8];
        }
        #pragma unroll
        for (int ni = 0; ni < 8; ni++) {
            int n0 = warp_n + ni * 8;
            bf[ni][0] = Bs[buf][k0 + lc][n0 + lr];
            bf[ni][1] = Bs[buf][k0 + 4 + lc][n0 + lr];
        }
        #pragma unroll
        for (int mi = 0; mi < 2; mi++)
            #pragma unroll
            for (int ni = 0; ni < 8; ni++)
                mma_tf32(acc[mi][ni], af[mi], bf[ni]);
    }

    if (dest == 0) {
        // fused loss_rank: scale by colscale, per-row online-softmax partials
        float sc[8][2];
        #pragma unroll
        for (int ni = 0; ni < 8; ni++) {
            int n = bn + warp_n + ni * 8 + lc * 2;
            sc[ni][0] = g_colscale[n];
            sc[ni][1] = g_colscale[n + 1];
        }
        #pragma unroll
        for (int mi = 0; mi < 2; mi++) {
            #pragma unroll
            for (int h = 0; h < 2; h++) {
                int rloc = warp_m + mi * 16 + h * 8 + lr;
                int r = bm + rloc;
                int lab = get_label(labels, r);
                float m = -1e30f;
                float vv[16];
                #pragma unroll
                for (int ni = 0; ni < 8; ni++) {
                    #pragma unroll
                    for (int j = 0; j < 2; j++) {
                        float v = acc[mi][ni][h * 2 + j] * sc[ni][j];
                        int col = bn + warp_n + ni * 8 + lc * 2 + j;
                        if (col == lab) g_rowlabel[r] = v;
                        vv[ni * 2 + j] = v;
                        m = fmaxf(m, v);
                    }
                }
                float s = 0.f;
                #pragma unroll
                for (int i = 0; i < 16; i++) s += __expf(vv[i] - m);
                // reduce across the 4 lanes (lc) sharing this row
                #pragma unroll
                for (int o = 1; o <= 2; o <<= 1) {
                    float m2 = __shfl_xor_sync(0xffffffffu, m, o);
                    float s2 = __shfl_xor_sync(0xffffffffu, s, o);
                    float M = fmaxf(m, m2);
                    s = s * __expf(m - M) + s2 * __expf(m2 - M);
                    m = M;
                }
                if (lc == 0) {
                    pm[rloc][wn_idx] = m;
                    ps[rloc][wn_idx] = s;
                }
            }
        }
        __syncthreads();
        if (tid < 128) {
            float m0 = pm[tid][0], m1 = pm[tid][1];
            float M = fmaxf(m0, m1);
            float s = ps[tid][0] * __expf(m0 - M) + ps[tid][1] * __expf(m1 - M);
            g_pmax[(size_t)(bm + tid) * NBLK + blockIdx.x] = M;
            g_psum[(size_t)(bm + tid) * NBLK + blockIdx.x] = s;
        }
    } else {
        float* Cg = (dest == 1) ? g_sim : g_tsim;
        #pragma unroll
        for (int mi = 0; mi < 2; mi++) {
            #pragma unroll
            for (int h = 0; h < 2; h++) {
                int r = bm + warp_m + mi * 16 + h * 8 + lr;
                #pragma unroll
                for (int ni = 0; ni < 8; ni++) {
                    int n = bn + warp_n + ni * 8 + lc * 2;
                    float2 v;
                    v.x = acc[mi][ni][h * 2 + 0];
                    v.y = acc[mi][ni][h * 2 + 1];
                    *(float2*)(Cg + (size_t)r * N + n) = v;
                }
            }
        }
    }
}

// merge the NBLK logsumexp partials per row; subtract the label logit
__global__ void rank_merge_kernel() {
    int b = blockIdx.x;
    int t = threadIdx.x;  // 128 threads
    __shared__ float sm[128], ss[128];
    sm[t] = g_pmax[(size_t)b * NBLK + t];
    ss[t] = g_psum[(size_t)b * NBLK + t];
    __syncthreads();
    for (int o = 64; o; o >>= 1) {
        if (t < o) {
            float m2 = sm[t + o], s2 = ss[t + o];
            float M = fmaxf(sm[t], m2);
            ss[t] = ss[t] * __expf(sm[t] - M) + s2 * __expf(m2 - M);
            sm[t] = M;
        }
        __syncthreads();
    }
    if (t == 0) g_rowrank[b] = sm[0] + logf(ss[0]) - g_rowlabel[b];
}

// per-row KD: scale = (same label ? 1 : 0.5)/TAU, softmax for s and t, KL sum
__global__ void kd_kernel(const int* __restrict__ labels) {
    int b = blockIdx.x;
    int t = threadIdx.x;
    __shared__ float zs[BSZ];
    __shared__ float zt[BSZ];
    __shared__ float red[256];

    int lb = get_label(labels, b);
    const float* srow = g_sim  + (size_t)b * BSZ;
    const float* trow = g_tsim + (size_t)b * BSZ;

    float ms = -1e30f, mt = -1e30f;
    for (int j = t; j < BSZ; j += 256) {
        float sc = (get_label(labels, j) == lb) ? 0.25f : 0.125f;  // 1/TAU, BETA/TAU
        float a = srow[j] * sc;
        float c = trow[j] * sc;
        zs[j] = a; zt[j] = c;
        ms = fmaxf(ms, a);
        mt = fmaxf(mt, c);
    }
    __syncthreads();

    red[t] = ms; __syncthreads();
    for (int o = 128; o; o >>= 1) { if (t < o) red[t] = fmaxf(red[t], red[t + o]); __syncthreads(); }
    ms = red[0]; __syncthreads();

    red[t] = mt; __syncthreads();
    for (int o = 128; o; o >>= 1) { if (t < o) red[t] = fmaxf(red[t], red[t + o]); __syncthreads(); }
    mt = red[0]; __syncthreads();

    float sums = 0.f, sumt = 0.f;
    for (int j = t; j < BSZ; j += 256) {
        sums += __expf(zs[j] - ms);
        sumt += __expf(zt[j] - mt);
    }
    red[t] = sums; __syncthreads();
    for (int o = 128; o; o >>= 1) { if (t < o) red[t] += red[t + o]; __syncthreads(); }
    sums = red[0]; __syncthreads();

    red[t] = sumt; __syncthreads();
    for (int o = 128; o; o >>= 1) { if (t < o) red[t] += red[t + o]; __syncthreads(); }
    sumt = red[0]; __syncthreads();

    float lss = logf(sums);
    float lst = logf(sumt);
    float kl = 0.f;
    for (int j = t; j < BSZ; j += 256) {
        float tl = zt[j] - mt - lst;
        float sl = zs[j] - ms - lss;
        kl += __expf(tl) * (tl - sl);
    }
    red[t] = kl; __syncthreads();
    for (int o = 128; o; o >>= 1) { if (t < o) red[t] += red[t + o]; __syncthreads(); }
    if (t == 0) g_rowkd[b] = red[0];
}

__global__ void final_kernel(const int* __restrict__ epoch_ptr, float* __restrict__ out,
                             int out_size) {
    __shared__ float r1[256], r2[256];
    int t = threadIdx.x;
    float a = 0.f, c = 0.f;
    for (int i = t; i < BSZ; i += 256) { a += g_rowrank[i]; c += g_rowkd[i]; }
    r1[t] = a; r2[t] = c;
    __syncthreads();
    for (int o = 128; o; o >>= 1) {
        if (t < o) { r1[t] += r1[t + o]; r2[t] += r2[t + o]; }
        __syncthreads();
    }
    if (t == 0) {
        float loss_rank = r1[0] * (1.0f / BSZ);
        float loss_kd   = r2[0] * (1.0f / BSZ);
        int epoch = epoch_ptr[0];  // low word valid for int32 and int64 encodings
        float ramp = ((float)epoch / 150.0f) * 16.0f;  // (epoch/N_EPOCHS)*ALPHA*TAU^2
        float loss = loss_rank + ramp * loss_kd;
        out[0] = loss;
        if (out_size > 1) out[1] = loss_rank;
        if (out_size > 2) out[2] = loss_kd;
    }
}

extern "C" void kernel_launch(void* const* d_in, const int* in_sizes, int n_in,
                              void* d_out, int out_size) {
    const float* batch   = (const float*)d_in[0];
    const float* teacher = (const float*)d_in[1];
    const float* cm      = (const float*)d_in[2];
    const int*   labels  = (const int*)d_in[3];
    const int*   epoch   = (const int*)d_in[4];
    float* out = (float*)d_out;

    colscale_kernel<<<CSZ / 8, 256>>>(cm);
    detect_labels_kernel<<<1, 256>>>(labels);

    dim3 grid1(CSZ / 128, BSZ / 128);
    gemm_tf32_kernel<<<grid1, 256>>>(batch, cm, ESZ, CSZ, 0, labels);

    dim3 grid2(BSZ / 128, BSZ / 128);
    gemm_tf32_kernel<<<grid2, 256>>>(batch, batch, ESZ, BSZ, 1, labels);
    gemm_tf32_kernel<<<grid2, 256>>>(teacher, teacher, ESZ, BSZ, 2, labels);

    rank_merge_kernel<<<BSZ, 128>>>();
    kd_kernel<<<BSZ, 256>>>(labels);
    final_kernel<<<1, 256>>>(epoch, out, out_size);
}

// round 10
// speedup vs baseline: 4.9422x; 4.8582x over previous
#include <cuda_runtime.h>
#include <cuda_bf16.h>
#include <cstdint>
#include <math.h>

#define BSZ 2048
#define ESZ 512
#define CSZ 16384
#define NBLK (CSZ / 128)

// ---------------- scratch (static device globals; no allocation) ----------------
__device__ float g_sim[(size_t)BSZ * BSZ];      // 16 MiB
__device__ float g_tsim[(size_t)BSZ * BSZ];     // 16 MiB
__device__ float g_pmax[(size_t)BSZ * NBLK];
__device__ float g_psum[(size_t)BSZ * NBLK];
__device__ float g_rowlabel[BSZ];
__device__ float g_colscale[CSZ];
__device__ float g_rowrank[BSZ];
__device__ float g_rowkd[BSZ];
__device__ int   g_lab64;
__device__ __nv_bfloat16 g_cmb[(size_t)CSZ * ESZ];  // 16 MiB bf16 class_map
__device__ __nv_bfloat16 g_ab[(size_t)BSZ * ESZ];   // 2 MiB bf16 batch
__device__ __nv_bfloat16 g_tb[(size_t)BSZ * ESZ];   // 2 MiB bf16 teacher

// Detect labels dtype: int64 LE with values <256 -> all odd int32 words zero.
__global__ void detect_labels_kernel(const int* __restrict__ labels) {
    __shared__ int cnt[256];
    int t = threadIdx.x;
    int c = 0;
    for (int i = t; i < BSZ; i += 256)
        if ((i & 1) && labels[i] != 0) c++;
    cnt[t] = c;
    __syncthreads();
    for (int o = 128; o; o >>= 1) {
        if (t < o) cnt[t] += cnt[t + o];
        __syncthreads();
    }
    if (t == 0) g_lab64 = (cnt[0] == 0) ? 1 : 0;
}

__device__ __forceinline__ int get_label(const int* __restrict__ labels, int b) {
    return g_lab64 ? labels[2 * b] : labels[b];
}

// per-class scale from fp32 class_map: rsqrt(||row||^2) / TEMPERATURE
__global__ void colscale_kernel(const float* __restrict__ cm) {
    int c = blockIdx.x * 8 + (threadIdx.x >> 5);
    int lane = threadIdx.x & 31;
    const float4* row = (const float4*)(cm + (size_t)c * ESZ);
    float s = 0.f;
    #pragma unroll 4
    for (int i = lane; i < ESZ / 4; i += 32) {
        float4 v = row[i];
        s += v.x * v.x + v.y * v.y + v.z * v.z + v.w * v.w;
    }
    #pragma unroll
    for (int o = 16; o; o >>= 1) s += __shfl_xor_sync(0xffffffffu, s, o);
    if (lane == 0) g_colscale[c] = rsqrtf(s) * 20.0f;
}

// fp32 -> bf16 conversion, 8 elts/thread, vectorized
__global__ void cvt_bf16_kernel(const float* __restrict__ src,
                                __nv_bfloat16* __restrict__ dst, int n8) {
    int i = blockIdx.x * 256 + threadIdx.x;
    if (i >= n8) return;
    float4 v0 = ((const float4*)src)[2 * i];
    float4 v1 = ((const float4*)src)[2 * i + 1];
    __nv_bfloat162 p0 = __floats2bfloat162_rn(v0.x, v0.y);
    __nv_bfloat162 p1 = __floats2bfloat162_rn(v0.z, v0.w);
    __nv_bfloat162 p2 = __floats2bfloat162_rn(v1.x, v1.y);
    __nv_bfloat162 p3 = __floats2bfloat162_rn(v1.z, v1.w);
    uint4 o;
    o.x = *(unsigned*)&p0; o.y = *(unsigned*)&p1;
    o.z = *(unsigned*)&p2; o.w = *(unsigned*)&p3;
    ((uint4*)dst)[i] = o;
}

// ---------------- helpers ----------------
__device__ __forceinline__ uint32_t smem_u32(const void* p) {
    uint32_t a;
    asm("{ .reg .u64 t; cvta.to.shared.u64 t, %1; cvt.u32.u64 %0, t; }"
        : "=r"(a) : "l"(p));
    return a;
}

__device__ __forceinline__ void ldsm_x4(unsigned& r0, unsigned& r1,
                                        unsigned& r2, unsigned& r3, uint32_t addr) {
    asm volatile("ldmatrix.sync.aligned.m8n8.x4.shared.b16 {%0,%1,%2,%3}, [%4];"
                 : "=r"(r0), "=r"(r1), "=r"(r2), "=r"(r3) : "r"(addr));
}

__device__ __forceinline__ void mma_bf16(float* d, const unsigned* a, const unsigned* b) {
    asm volatile(
        "mma.sync.aligned.m16n8k16.row.col.f32.bf16.bf16.f32 "
        "{%0,%1,%2,%3}, {%4,%5,%6,%7}, {%8,%9}, {%0,%1,%2,%3};\n"
        : "+f"(d[0]), "+f"(d[1]), "+f"(d[2]), "+f"(d[3])
        : "r"(a[0]), "r"(a[1]), "r"(a[2]), "r"(a[3]), "r"(b[0]), "r"(b[1]));
}

// swizzled byte offset of 16B chunk (row, c) in a 128x32 bf16 tile (64B pitch)
__device__ __forceinline__ int tile_off(int row, int c) {
    return row * 64 + ((c ^ ((row >> 1) & 3)) << 4);
}

// ---------------- bf16 tensor-core NT GEMM ----------------
// C[m,n] = sum_k A[m,k]*B[n,k]; A,B bf16 row-major [.,K], K=512.
// BM=BN=128, BK=32, 256 threads = 8 warps (4m x 2n), warp tile 32x64.
// dest==0: fused logits epilogue (colscale + per-row online-softmax partials).
// dest==1/2: store fp32 C to g_sim / g_tsim.
__global__ void __launch_bounds__(256, 2) gemm_bf16_kernel(
    const __nv_bfloat16* __restrict__ A, const __nv_bfloat16* __restrict__ Bm,
    int K, int N, int dest, const int* __restrict__ labels)
{
    __shared__ __align__(16) __nv_bfloat16 As[2][128 * 32];
    __shared__ __align__(16) __nv_bfloat16 Bs[2][128 * 32];
    __shared__ float pm[128][2];
    __shared__ float ps[128][2];

    int tid  = threadIdx.x;
    int lane = tid & 31;
    int wid  = tid >> 5;
    int warp_m = (wid >> 1) * 32;
    int wn_idx = wid & 1;
    int warp_n = wn_idx * 64;
    int lr = lane >> 2;
    int lc = lane & 3;

    int bm = blockIdx.y * 128;
    int bn = blockIdx.x * 128;

    uint32_t as_base = smem_u32(As);
    uint32_t bs_base = smem_u32(Bs);

    // ldmatrix per-lane address components
    // A frag: groups: 0:(m+l, c0) 1:(m+8+l, c0) 2:(m+l, c1) 3:(m+8+l, c1)
    int rA    = (((lane >> 3) & 1) << 3) + (lane & 7);
    int cbitA = lane >> 4;
    // B frag: groups: 0:(n+l, c0) 1:(n+l, c1) 2:(n+8+l, c0) 3:(n+8+l, c1)
    int rB    = ((lane >> 4) << 3) + (lane & 7);
    int cbitB = (lane >> 3) & 1;

    int rowA[2], swA[2];
    #pragma unroll
    for (int mi = 0; mi < 2; mi++) {
        rowA[mi] = warp_m + mi * 16 + rA;
        swA[mi]  = (rowA[mi] >> 1) & 3;
    }
    int rowB[4], swB[4];
    #pragma unroll
    for (int nj = 0; nj < 4; nj++) {
        rowB[nj] = warp_n + nj * 16 + rB;
        swB[nj]  = (rowB[nj] >> 1) & 3;
    }

    // global chunk mapping: thread handles 16B chunks tid and tid+256 (of 512)
    int r0c = tid >> 2,         c0c = tid & 3;
    int r1c = (tid + 256) >> 2, c1c = tid & 3;
    const uint4* Ag = (const uint4*)A;
    const uint4* Bg = (const uint4*)Bm;
    int ldg4 = K >> 3;  // uint4 per row
    const uint4* Ap0 = Ag + (size_t)(bm + r0c) * ldg4 + c0c;
    const uint4* Ap1 = Ag + (size_t)(bm + r1c) * ldg4 + c1c;
    const uint4* Bp0 = Bg + (size_t)(bn + r0c) * ldg4 + c0c;
    const uint4* Bp1 = Bg + (size_t)(bn + r1c) * ldg4 + c1c;
    int sA0 = tile_off(r0c, c0c), sA1 = tile_off(r1c, c1c);

    float acc[2][8][4];
    #pragma unroll
    for (int mi = 0; mi < 2; mi++)
        #pragma unroll
        for (int ni = 0; ni < 8; ni++)
            #pragma unroll
            for (int j = 0; j < 4; j++) acc[mi][ni][j] = 0.f;

    uint4 va0, va1, vb0, vb1;
    va0 = Ap0[0]; va1 = Ap1[0]; vb0 = Bp0[0]; vb1 = Bp1[0];
    *(uint4*)((char*)As[0] + sA0) = va0;
    *(uint4*)((char*)As[0] + sA1) = va1;
    *(uint4*)((char*)Bs[0] + sA0) = vb0;
    *(uint4*)((char*)Bs[0] + sA1) = vb1;
    __syncthreads();

    int buf = 0;
    int ntiles = K / 32;
    for (int kt = 1; kt <= ntiles; kt++) {
        if (kt < ntiles) {
            va0 = Ap0[kt * 4]; va1 = Ap1[kt * 4];
            vb0 = Bp0[kt * 4]; vb1 = Bp1[kt * 4];
        }
        uint32_t ab = as_base + buf * 8192;
        uint32_t bb = bs_base + buf * 8192;
        #pragma unroll
        for (int ks = 0; ks < 2; ks++) {
            unsigned af[2][4], bfr[4][4];
            #pragma unroll
            for (int mi = 0; mi < 2; mi++) {
                int c = 2 * ks + cbitA;
                uint32_t ad = ab + rowA[mi] * 64 + (((c ^ swA[mi]) & 3) << 4);
                ldsm_x4(af[mi][0], af[mi][1], af[mi][2], af[mi][3], ad);
            }
            #pragma unroll
            for (int nj = 0; nj < 4; nj++) {
                int c = 2 * ks + cbitB;
                uint32_t ad = bb + rowB[nj] * 64 + (((c ^ swB[nj]) & 3) << 4);
                ldsm_x4(bfr[nj][0], bfr[nj][1], bfr[nj][2], bfr[nj][3], ad);
            }
            #pragma unroll
            for (int mi = 0; mi < 2; mi++)
                #pragma unroll
                for (int ni = 0; ni < 8; ni++)
                    mma_bf16(acc[mi][ni], af[mi], &bfr[ni >> 1][(ni & 1) * 2]);
        }
        if (kt < ntiles) {
            int nb = buf ^ 1;
            *(uint4*)((char*)As[nb] + sA0) = va0;
            *(uint4*)((char*)As[nb] + sA1) = va1;
            *(uint4*)((char*)Bs[nb] + sA0) = vb0;
            *(uint4*)((char*)Bs[nb] + sA1) = vb1;
            __syncthreads();
            buf = nb;
        }
    }

    if (dest == 0) {
        float sc[8][2];
        #pragma unroll
        for (int ni = 0; ni < 8; ni++) {
            int n = bn + warp_n + ni * 8 + lc * 2;
            sc[ni][0] = g_colscale[n];
            sc[ni][1] = g_colscale[n + 1];
        }
        #pragma unroll
        for (int mi = 0; mi < 2; mi++) {
            #pragma unroll
            for (int h = 0; h < 2; h++) {
                int rloc = warp_m + mi * 16 + h * 8 + lr;
                int r = bm + rloc;
                int lab = get_label(labels, r);
                float m = -1e30f;
                float vv[16];
                #pragma unroll
                for (int ni = 0; ni < 8; ni++) {
                    #pragma unroll
                    for (int j = 0; j < 2; j++) {
                        float v = acc[mi][ni][h * 2 + j] * sc[ni][j];
                        int col = bn + warp_n + ni * 8 + lc * 2 + j;
                        if (col == lab) g_rowlabel[r] = v;
                        vv[ni * 2 + j] = v;
                        m = fmaxf(m, v);
                    }
                }
                float s = 0.f;
                #pragma unroll
                for (int i = 0; i < 16; i++) s += __expf(vv[i] - m);
                #pragma unroll
                for (int o = 1; o <= 2; o <<= 1) {
                    float m2 = __shfl_xor_sync(0xffffffffu, m, o);
                    float s2 = __shfl_xor_sync(0xffffffffu, s, o);
                    float M = fmaxf(m, m2);
                    s = s * __expf(m - M) + s2 * __expf(m2 - M);
                    m = M;
                }
                if (lc == 0) {
                    pm[rloc][wn_idx] = m;
                    ps[rloc][wn_idx] = s;
                }
            }
        }
        __syncthreads();
        if (tid < 128) {
            float m0 = pm[tid][0], m1 = pm[tid][1];
            float M = fmaxf(m0, m1);
            float s = ps[tid][0] * __expf(m0 - M) + ps[tid][1] * __expf(m1 - M);
            g_pmax[(size_t)(bm + tid) * NBLK + blockIdx.x] = M;
            g_psum[(size_t)(bm + tid) * NBLK + blockIdx.x] = s;
        }
    } else {
        float* Cg = (dest == 1) ? g_sim : g_tsim;
        #pragma unroll
        for (int mi = 0; mi < 2; mi++) {
            #pragma unroll
            for (int h = 0; h < 2; h++) {
                int r = bm + warp_m + mi * 16 + h * 8 + lr;
                #pragma unroll
                for (int ni = 0; ni < 8; ni++) {
                    int n = bn + warp_n + ni * 8 + lc * 2;
                    float2 v;
                    v.x = acc[mi][ni][h * 2 + 0];
                    v.y = acc[mi][ni][h * 2 + 1];
                    *(float2*)(Cg + (size_t)r * N + n) = v;
                }
            }
        }
    }
}

// merge the NBLK logsumexp partials per row; subtract the label logit
__global__ void rank_merge_kernel() {
    int b = blockIdx.x;
    int t = threadIdx.x;
    __shared__ float sm[128], ss[128];
    sm[t] = g_pmax[(size_t)b * NBLK + t];
    ss[t] = g_psum[(size_t)b * NBLK + t];
    __syncthreads();
    for (int o = 64; o; o >>= 1) {
        if (t < o) {
            float m2 = sm[t + o], s2 = ss[t + o];
            float M = fmaxf(sm[t], m2);
            ss[t] = ss[t] * __expf(sm[t] - M) + s2 * __expf(m2 - M);
            sm[t] = M;
        }
        __syncthreads();
    }
    if (t == 0) g_rowrank[b] = sm[0] + logf(ss[0]) - g_rowlabel[b];
}

// per-row KD: scale = (same label ? 1 : 0.5)/TAU, softmax for s and t, KL sum
__global__ void kd_kernel(const int* __restrict__ labels) {
    int b = blockIdx.x;
    int t = threadIdx.x;
    __shared__ float zs[BSZ];
    __shared__ float zt[BSZ];
    __shared__ float red[256];

    int lb = get_label(labels, b);
    const float* srow = g_sim  + (size_t)b * BSZ;
    const float* trow = g_tsim + (size_t)b * BSZ;

    float ms = -1e30f, mt = -1e30f;
    for (int j = t; j < BSZ; j += 256) {
        float sc = (get_label(labels, j) == lb) ? 0.25f : 0.125f;
        float a = srow[j] * sc;
        float c = trow[j] * sc;
        zs[j] = a; zt[j] = c;
        ms = fmaxf(ms, a);
        mt = fmaxf(mt, c);
    }
    __syncthreads();

    red[t] = ms; __syncthreads();
    for (int o = 128; o; o >>= 1) { if (t < o) red[t] = fmaxf(red[t], red[t + o]); __syncthreads(); }
    ms = red[0]; __syncthreads();

    red[t] = mt; __syncthreads();
    for (int o = 128; o; o >>= 1) { if (t < o) red[t] = fmaxf(red[t], red[t + o]); __syncthreads(); }
    mt = red[0]; __syncthreads();

    float sums = 0.f, sumt = 0.f;
    for (int j = t; j < BSZ; j += 256) {
        sums += __expf(zs[j] - ms);
        sumt += __expf(zt[j] - mt);
    }
    red[t] = sums; __syncthreads();
    for (int o = 128; o; o >>= 1) { if (t < o) red[t] += red[t + o]; __syncthreads(); }
    sums = red[0]; __syncthreads();

    red[t] = sumt; __syncthreads();
    for (int o = 128; o; o >>= 1) { if (t < o) red[t] += red[t + o]; __syncthreads(); }
    sumt = red[0]; __syncthreads();

    float lss = logf(sums);
    float lst = logf(sumt);
    float kl = 0.f;
    for (int j = t; j < BSZ; j += 256) {
        float tl = zt[j] - mt - lst;
        float sl = zs[j] - ms - lss;
        kl += __expf(tl) * (tl - sl);
    }
    red[t] = kl; __syncthreads();
    for (int o = 128; o; o >>= 1) { if (t < o) red[t] += red[t + o]; __syncthreads(); }
    if (t == 0) g_rowkd[b] = red[0];
}

__global__ void final_kernel(const int* __restrict__ epoch_ptr, float* __restrict__ out,
                             int out_size) {
    __shared__ float r1[256], r2[256];
    int t = threadIdx.x;
    float a = 0.f, c = 0.f;
    for (int i = t; i < BSZ; i += 256) { a += g_rowrank[i]; c += g_rowkd[i]; }
    r1[t] = a; r2[t] = c;
    __syncthreads();
    for (int o = 128; o; o >>= 1) {
        if (t < o) { r1[t] += r1[t + o]; r2[t] += r2[t + o]; }
        __syncthreads();
    }
    if (t == 0) {
        float loss_rank = r1[0] * (1.0f / BSZ);
        float loss_kd   = r2[0] * (1.0f / BSZ);
        int epoch = epoch_ptr[0];
        float ramp = ((float)epoch / 150.0f) * 16.0f;
        float loss = loss_rank + ramp * loss_kd;
        out[0] = loss;
        if (out_size > 1) out[1] = loss_rank;
        if (out_size > 2) out[2] = loss_kd;
    }
}

extern "C" void kernel_launch(void* const* d_in, const int* in_sizes, int n_in,
                              void* d_out, int out_size) {
    const float* batch   = (const float*)d_in[0];
    const float* teacher = (const float*)d_in[1];
    const float* cm      = (const float*)d_in[2];
    const int*   labels  = (const int*)d_in[3];
    const int*   epoch   = (const int*)d_in[4];
    float* out = (float*)d_out;

    colscale_kernel<<<CSZ / 8, 256>>>(cm);
    detect_labels_kernel<<<1, 256>>>(labels);

    // bf16 pre-conversion
    __nv_bfloat16 *cmb, *ab, *tb;
    cudaGetSymbolAddress((void**)&cmb, g_cmb);
    cudaGetSymbolAddress((void**)&ab,  g_ab);
    cudaGetSymbolAddress((void**)&tb,  g_tb);
    cvt_bf16_kernel<<<(CSZ * ESZ / 8 + 255) / 256, 256>>>(cm, cmb, CSZ * ESZ / 8);
    cvt_bf16_kernel<<<(BSZ * ESZ / 8 + 255) / 256, 256>>>(batch, ab, BSZ * ESZ / 8);
    cvt_bf16_kernel<<<(BSZ * ESZ / 8 + 255) / 256, 256>>>(teacher, tb, BSZ * ESZ / 8);

    dim3 grid1(CSZ / 128, BSZ / 128);
    gemm_bf16_kernel<<<grid1, 256>>>(ab, cmb, ESZ, CSZ, 0, labels);

    dim3 grid2(BSZ / 128, BSZ / 128);
    gemm_bf16_kernel<<<grid2, 256>>>(ab, ab, ESZ, BSZ, 1, labels);
    gemm_bf16_kernel<<<grid2, 256>>>(tb, tb, ESZ, BSZ, 2, labels);

    rank_merge_kernel<<<BSZ, 128>>>();
    kd_kernel<<<BSZ, 256>>>(labels);
    final_kernel<<<1, 256>>>(epoch, out, out_size);
}

// round 13
// speedup vs baseline: 6.1502x; 1.2444x over previous
#include <cuda_runtime.h>
#include <cuda_bf16.h>
#include <cstdint>
#include <math.h>

#define BSZ 2048
#define ESZ 512
#define CSZ 16384
#define NBLK (CSZ / 128)
#define NSTAGE 3
#define NTILES (ESZ / 32)   // 16 K-tiles

// ---------------- scratch (static device globals; no allocation) ----------------
__device__ float g_sim[(size_t)BSZ * BSZ];      // 16 MiB
__device__ float g_tsim[(size_t)BSZ * BSZ];     // 16 MiB
__device__ float g_pmax[(size_t)BSZ * NBLK];
__device__ float g_psum[(size_t)BSZ * NBLK];
__device__ float g_rowlabel[BSZ];
__device__ float g_colscale[CSZ];
__device__ float g_rowrank[BSZ];
__device__ float g_rowkd[BSZ];
__device__ int   g_lab64;
__device__ __nv_bfloat16 g_cmb[(size_t)CSZ * ESZ];  // 16 MiB bf16 class_map
__device__ __nv_bfloat16 g_ab[(size_t)BSZ * ESZ];   // 2 MiB bf16 batch
__device__ __nv_bfloat16 g_tb[(size_t)BSZ * ESZ];   // 2 MiB bf16 teacher

// Detect labels dtype: int64 LE with values <256 -> all odd int32 words zero.
__global__ void detect_labels_kernel(const int* __restrict__ labels) {
    __shared__ int cnt[256];
    int t = threadIdx.x;
    int c = 0;
    for (int i = t; i < BSZ; i += 256)
        if ((i & 1) && labels[i] != 0) c++;
    cnt[t] = c;
    __syncthreads();
    for (int o = 128; o; o >>= 1) {
        if (t < o) cnt[t] += cnt[t + o];
        __syncthreads();
    }
    if (t == 0) g_lab64 = (cnt[0] == 0) ? 1 : 0;
}

__device__ __forceinline__ int get_label(const int* __restrict__ labels, int b) {
    return g_lab64 ? labels[2 * b] : labels[b];
}

// per-class scale from fp32 class_map: rsqrt(||row||^2) / TEMPERATURE
__global__ void colscale_kernel(const float* __restrict__ cm) {
    int c = blockIdx.x * 8 + (threadIdx.x >> 5);
    int lane = threadIdx.x & 31;
    const float4* row = (const float4*)(cm + (size_t)c * ESZ);
    float s = 0.f;
    #pragma unroll 4
    for (int i = lane; i < ESZ / 4; i += 32) {
        float4 v = row[i];
        s += v.x * v.x + v.y * v.y + v.z * v.z + v.w * v.w;
    }
    #pragma unroll
    for (int o = 16; o; o >>= 1) s += __shfl_xor_sync(0xffffffffu, s, o);
    if (lane == 0) g_colscale[c] = rsqrtf(s) * 20.0f;
}

// fp32 -> bf16 conversion, 8 elts/thread, vectorized
__global__ void cvt_bf16_kernel(const float* __restrict__ src,
                                __nv_bfloat16* __restrict__ dst, int n8) {
    int i = blockIdx.x * 256 + threadIdx.x;
    if (i >= n8) return;
    float4 v0 = ((const float4*)src)[2 * i];
    float4 v1 = ((const float4*)src)[2 * i + 1];
    __nv_bfloat162 p0 = __floats2bfloat162_rn(v0.x, v0.y);
    __nv_bfloat162 p1 = __floats2bfloat162_rn(v0.z, v0.w);
    __nv_bfloat162 p2 = __floats2bfloat162_rn(v1.x, v1.y);
    __nv_bfloat162 p3 = __floats2bfloat162_rn(v1.z, v1.w);
    uint4 o;
    o.x = *(unsigned*)&p0; o.y = *(unsigned*)&p1;
    o.z = *(unsigned*)&p2; o.w = *(unsigned*)&p3;
    ((uint4*)dst)[i] = o;
}

// ---------------- helpers ----------------
__device__ __forceinline__ uint32_t smem_u32(const void* p) {
    uint32_t a;
    asm("{ .reg .u64 t; cvta.to.shared.u64 t, %1; cvt.u32.u64 %0, t; }"
        : "=r"(a) : "l"(p));
    return a;
}

__device__ __forceinline__ void cp_async16(uint32_t saddr, const void* gptr) {
    asm volatile("cp.async.cg.shared.global [%0], [%1], 16;"
                 :: "r"(saddr), "l"(gptr));
}
__device__ __forceinline__ void cp_commit() {
    asm volatile("cp.async.commit_group;");
}
template <int N>
__device__ __forceinline__ void cp_wait() {
    asm volatile("cp.async.wait_group %0;" :: "n"(N));
}

__device__ __forceinline__ void ldsm_x4(unsigned& r0, unsigned& r1,
                                        unsigned& r2, unsigned& r3, uint32_t addr) {
    asm volatile("ldmatrix.sync.aligned.m8n8.x4.shared.b16 {%0,%1,%2,%3}, [%4];"
                 : "=r"(r0), "=r"(r1), "=r"(r2), "=r"(r3) : "r"(addr));
}

__device__ __forceinline__ void mma_bf16(float* d, const unsigned* a, const unsigned* b) {
    asm volatile(
        "mma.sync.aligned.m16n8k16.row.col.f32.bf16.bf16.f32 "
        "{%0,%1,%2,%3}, {%4,%5,%6,%7}, {%8,%9}, {%0,%1,%2,%3};\n"
        : "+f"(d[0]), "+f"(d[1]), "+f"(d[2]), "+f"(d[3])
        : "r"(a[0]), "r"(a[1]), "r"(a[2]), "r"(a[3]), "r"(b[0]), "r"(b[1]));
}

// swizzled byte offset of 16B chunk (row, c) in a 128x32 bf16 tile (64B pitch)
__device__ __forceinline__ int tile_off(int row, int c) {
    return row * 64 + ((c ^ ((row >> 1) & 3)) << 4);
}

// ---------------- bf16 tensor-core NT GEMM, cp.async 3-stage ----------------
// C[m,n] = sum_k A[m,k]*B[n,k]; bf16 row-major [., 512].
// BM=BN=128, BK=32, 256 threads = 8 warps (4m x 2n), warp tile 32x64.
// dest==0: fused logits epilogue. dest==1: sim/tsim pair via blockIdx.z.
__global__ void __launch_bounds__(256, 2) gemm_bf16_kernel(
    const __nv_bfloat16* __restrict__ A0, const __nv_bfloat16* __restrict__ B0,
    const __nv_bfloat16* __restrict__ A1, const __nv_bfloat16* __restrict__ B1,
    int N, int dest, const int* __restrict__ labels)
{
    __shared__ __align__(16) __nv_bfloat16 As[NSTAGE][128 * 32];  // 8 KB/stage
    __shared__ __align__(16) __nv_bfloat16 Bs[NSTAGE][128 * 32];  // 8 KB/stage

    const __nv_bfloat16* A = (dest == 1 && blockIdx.z == 1) ? A1 : A0;
    const __nv_bfloat16* Bm = (dest == 1 && blockIdx.z == 1) ? B1 : B0;

    int tid  = threadIdx.x;
    int lane = tid & 31;
    int wid  = tid >> 5;
    int warp_m = (wid >> 1) * 32;
    int wn_idx = wid & 1;
    int warp_n = wn_idx * 64;
    int lr = lane >> 2;
    int lc = lane & 3;

    int bm = blockIdx.y * 128;
    int bn = blockIdx.x * 128;

    uint32_t as_base = smem_u32(As);
    uint32_t bs_base = smem_u32(Bs);

    // ldmatrix per-lane address components
    int rA    = (((lane >> 3) & 1) << 3) + (lane & 7);
    int cbitA = lane >> 4;
    int rB    = ((lane >> 4) << 3) + (lane & 7);
    int cbitB = (lane >> 3) & 1;

    int rowA[2], swA[2];
    #pragma unroll
    for (int mi = 0; mi < 2; mi++) {
        rowA[mi] = warp_m + mi * 16 + rA;
        swA[mi]  = (rowA[mi] >> 1) & 3;
    }
    int rowB[4], swB[4];
    #pragma unroll
    for (int nj = 0; nj < 4; nj++) {
        rowB[nj] = warp_n + nj * 16 + rB;
        swB[nj]  = (rowB[nj] >> 1) & 3;
    }

    // global chunk mapping: thread owns 16B chunks tid and tid+256 (of 512)
    int r0c = tid >> 2,         c0c = tid & 3;
    int r1c = (tid + 256) >> 2, c1c = tid & 3;
    const int ldg4 = ESZ >> 3;  // uint4 per row = 64
    const uint4* Ap0 = (const uint4*)A + (size_t)(bm + r0c) * ldg4 + c0c;
    const uint4* Ap1 = (const uint4*)A + (size_t)(bm + r1c) * ldg4 + c1c;
    const uint4* Bp0 = (const uint4*)Bm + (size_t)(bn + r0c) * ldg4 + c0c;
    const uint4* Bp1 = (const uint4*)Bm + (size_t)(bn + r1c) * ldg4 + c1c;
    int sA0 = tile_off(r0c, c0c), sA1 = tile_off(r1c, c1c);

    float acc[2][8][4];
    #pragma unroll
    for (int mi = 0; mi < 2; mi++)
        #pragma unroll
        for (int ni = 0; ni < 8; ni++)
            #pragma unroll
            for (int j = 0; j < 4; j++) acc[mi][ni][j] = 0.f;

    // prologue: async-fill stages 0 and 1
    #pragma unroll
    for (int s = 0; s < 2; s++) {
        uint32_t ab = as_base + s * 8192;
        uint32_t bb = bs_base + s * 8192;
        cp_async16(ab + sA0, Ap0 + s * 4);
        cp_async16(ab + sA1, Ap1 + s * 4);
        cp_async16(bb + sA0, Bp0 + s * 4);
        cp_async16(bb + sA1, Bp1 + s * 4);
        cp_commit();
    }
    cp_wait<1>();
    __syncthreads();

    #pragma unroll
    for (int kt = 0; kt < NTILES; kt++) {
        int buf = kt % NSTAGE;
        uint32_t ab = as_base + buf * 8192;
        uint32_t bb = bs_base + buf * 8192;
        #pragma unroll
        for (int ks = 0; ks < 2; ks++) {
            unsigned af[2][4], bfr[4][4];
            #pragma unroll
            for (int mi = 0; mi < 2; mi++) {
                int c = 2 * ks + cbitA;
                uint32_t ad = ab + rowA[mi] * 64 + (((c ^ swA[mi]) & 3) << 4);
                ldsm_x4(af[mi][0], af[mi][1], af[mi][2], af[mi][3], ad);
            }
            #pragma unroll
            for (int nj = 0; nj < 4; nj++) {
                int c = 2 * ks + cbitB;
                uint32_t ad = bb + rowB[nj] * 64 + (((c ^ swB[nj]) & 3) << 4);
                ldsm_x4(bfr[nj][0], bfr[nj][1], bfr[nj][2], bfr[nj][3], ad);
            }
            #pragma unroll
            for (int mi = 0; mi < 2; mi++)
                #pragma unroll
                for (int ni = 0; ni < 8; ni++)
                    mma_bf16(acc[mi][ni], af[mi], &bfr[ni >> 1][(ni & 1) * 2]);
        }
        int nk = kt + 2;
        if (nk < NTILES) {
            int nb = nk % NSTAGE;
            uint32_t nab = as_base + nb * 8192;
            uint32_t nbb = bs_base + nb * 8192;
            cp_async16(nab + sA0, Ap0 + nk * 4);
            cp_async16(nab + sA1, Ap1 + nk * 4);
            cp_async16(nbb + sA0, Bp0 + nk * 4);
            cp_async16(nbb + sA1, Bp1 + nk * 4);
            cp_commit();
            cp_wait<1>();
        } else {
            cp_wait<0>();
        }
        __syncthreads();
    }

    if (dest == 0) {
        // pm/ps alias the (now dead) stage-0 smem
        float (*pm)[2] = (float(*)[2])&As[0][0];
        float (*ps)[2] = (float(*)[2])&As[0][512];
        float sc[8][2];
        #pragma unroll
        for (int ni = 0; ni < 8; ni++) {
            int n = bn + warp_n + ni * 8 + lc * 2;
            sc[ni][0] = g_colscale[n];
            sc[ni][1] = g_colscale[n + 1];
        }
        #pragma unroll
        for (int mi = 0; mi < 2; mi++) {
            #pragma unroll
            for (int h = 0; h < 2; h++) {
                int rloc = warp_m + mi * 16 + h * 8 + lr;
                int r = bm + rloc;
                int lab = get_label(labels, r);
                float m = -1e30f;
                float vv[16];
                #pragma unroll
                for (int ni = 0; ni < 8; ni++) {
                    #pragma unroll
                    for (int j = 0; j < 2; j++) {
                        float v = acc[mi][ni][h * 2 + j] * sc[ni][j];
                        int col = bn + warp_n + ni * 8 + lc * 2 + j;
                        if (col == lab) g_rowlabel[r] = v;
                        vv[ni * 2 + j] = v;
                        m = fmaxf(m, v);
                    }
                }
                float s = 0.f;
                #pragma unroll
                for (int i = 0; i < 16; i++) s += __expf(vv[i] - m);
                #pragma unroll
                for (int o = 1; o <= 2; o <<= 1) {
                    float m2 = __shfl_xor_sync(0xffffffffu, m, o);
                    float s2 = __shfl_xor_sync(0xffffffffu, s, o);
                    float M = fmaxf(m, m2);
                    s = s * __expf(m - M) + s2 * __expf(m2 - M);
                    m = M;
                }
                if (lc == 0) {
                    pm[rloc][wn_idx] = m;
                    ps[rloc][wn_idx] = s;
                }
            }
        }
        __syncthreads();
        if (tid < 128) {
            float m0 = pm[tid][0], m1 = pm[tid][1];
            float M = fmaxf(m0, m1);
            float s = ps[tid][0] * __expf(m0 - M) + ps[tid][1] * __expf(m1 - M);
            g_pmax[(size_t)(bm + tid) * NBLK + blockIdx.x] = M;
            g_psum[(size_t)(bm + tid) * NBLK + blockIdx.x] = s;
        }
    } else {
        float* Cg = (blockIdx.z == 1) ? g_tsim : g_sim;
        #pragma unroll
        for (int mi = 0; mi < 2; mi++) {
            #pragma unroll
            for (int h = 0; h < 2; h++) {
                int r = bm + warp_m + mi * 16 + h * 8 + lr;
                #pragma unroll
                for (int ni = 0; ni < 8; ni++) {
                    int n = bn + warp_n + ni * 8 + lc * 2;
                    float2 v;
                    v.x = acc[mi][ni][h * 2 + 0];
                    v.y = acc[mi][ni][h * 2 + 1];
                    *(float2*)(Cg + (size_t)r * N + n) = v;
                }
            }
        }
    }
}

// merge the NBLK logsumexp partials per row; subtract the label logit
__global__ void rank_merge_kernel() {
    int b = blockIdx.x;
    int t = threadIdx.x;
    __shared__ float sm[128], ss[128];
    sm[t] = g_pmax[(size_t)b * NBLK + t];
    ss[t] = g_psum[(size_t)b * NBLK + t];
    __syncthreads();
    for (int o = 64; o; o >>= 1) {
        if (t < o) {
            float m2 = sm[t + o], s2 = ss[t + o];
            float M = fmaxf(sm[t], m2);
            ss[t] = ss[t] * __expf(sm[t] - M) + s2 * __expf(m2 - M);
            sm[t] = M;
        }
        __syncthreads();
    }
    if (t == 0) g_rowrank[b] = sm[0] + logf(ss[0]) - g_rowlabel[b];
}

// per-row KD: scale = (same label ? 1 : 0.5)/TAU, softmax for s and t, KL sum
__global__ void kd_kernel(const int* __restrict__ labels) {
    int b = blockIdx.x;
    int t = threadIdx.x;
    __shared__ float zs[BSZ];
    __shared__ float zt[BSZ];
    __shared__ float red[256];

    int lb = get_label(labels, b);
    const float* srow = g_sim  + (size_t)b * BSZ;
    const float* trow = g_tsim + (size_t)b * BSZ;

    float ms = -1e30f, mt = -1e30f;
    for (int j = t; j < BSZ; j += 256) {
        float sc = (get_label(labels, j) == lb) ? 0.25f : 0.125f;
        float a = srow[j] * sc;
        float c = trow[j] * sc;
        zs[j] = a; zt[j] = c;
        ms = fmaxf(ms, a);
        mt = fmaxf(mt, c);
    }
    __syncthreads();

    red[t] = ms; __syncthreads();
    for (int o = 128; o; o >>= 1) { if (t < o) red[t] = fmaxf(red[t], red[t + o]); __syncthreads(); }
    ms = red[0]; __syncthreads();

    red[t] = mt; __syncthreads();
    for (int o = 128; o; o >>= 1) { if (t < o) red[t] = fmaxf(red[t], red[t + o]); __syncthreads(); }
    mt = red[0]; __syncthreads();

    float sums = 0.f, sumt = 0.f;
    for (int j = t; j < BSZ; j += 256) {
        sums += __expf(zs[j] - ms);
        sumt += __expf(zt[j] - mt);
    }
    red[t] = sums; __syncthreads();
    for (int o = 128; o; o >>= 1) { if (t < o) red[t] += red[t + o]; __syncthreads(); }
    sums = red[0]; __syncthreads();

    red[t] = sumt; __syncthreads();
    for (int o = 128; o; o >>= 1) { if (t < o) red[t] += red[t + o]; __syncthreads(); }
    sumt = red[0]; __syncthreads();

    float lss = logf(sums);
    float lst = logf(sumt);
    float kl = 0.f;
    for (int j = t; j < BSZ; j += 256) {
        float tl = zt[j] - mt - lst;
        float sl = zs[j] - ms - lss;
        kl += __expf(tl) * (tl - sl);
    }
    red[t] = kl; __syncthreads();
    for (int o = 128; o; o >>= 1) { if (t < o) red[t] += red[t + o]; __syncthreads(); }
    if (t == 0) g_rowkd[b] = red[0];
}

__global__ void final_kernel(const int* __restrict__ epoch_ptr, float* __restrict__ out,
                             int out_size) {
    __shared__ float r1[256], r2[256];
    int t = threadIdx.x;
    float a = 0.f, c = 0.f;
    for (int i = t; i < BSZ; i += 256) { a += g_rowrank[i]; c += g_rowkd[i]; }
    r1[t] = a; r2[t] = c;
    __syncthreads();
    for (int o = 128; o; o >>= 1) {
        if (t < o) { r1[t] += r1[t + o]; r2[t] += r2[t + o]; }
        __syncthreads();
    }
    if (t == 0) {
        float loss_rank = r1[0] * (1.0f / BSZ);
        float loss_kd   = r2[0] * (1.0f / BSZ);
        int epoch = epoch_ptr[0];
        float ramp = ((float)epoch / 150.0f) * 16.0f;
        float loss = loss_rank + ramp * loss_kd;
        out[0] = loss;
        if (out_size > 1) out[1] = loss_rank;
        if (out_size > 2) out[2] = loss_kd;
    }
}

extern "C" void kernel_launch(void* const* d_in, const int* in_sizes, int n_in,
                              void* d_out, int out_size) {
    const float* batch   = (const float*)d_in[0];
    const float* teacher = (const float*)d_in[1];
    const float* cm      = (const float*)d_in[2];
    const int*   labels  = (const int*)d_in[3];
    const int*   epoch   = (const int*)d_in[4];
    float* out = (float*)d_out;

    colscale_kernel<<<CSZ / 8, 256>>>(cm);
    detect_labels_kernel<<<1, 256>>>(labels);

    __nv_bfloat16 *cmb, *ab, *tb;
    cudaGetSymbolAddress((void**)&cmb, g_cmb);
    cudaGetSymbolAddress((void**)&ab,  g_ab);
    cudaGetSymbolAddress((void**)&tb,  g_tb);
    cvt_bf16_kernel<<<(CSZ * ESZ / 8 + 255) / 256, 256>>>(cm, cmb, CSZ * ESZ / 8);
    cvt_bf16_kernel<<<(BSZ * ESZ / 8 + 255) / 256, 256>>>(batch, ab, BSZ * ESZ / 8);
    cvt_bf16_kernel<<<(BSZ * ESZ / 8 + 255) / 256, 256>>>(teacher, tb, BSZ * ESZ / 8);

    // logits GEMM + fused loss_rank partials
    dim3 grid1(CSZ / 128, BSZ / 128, 1);
    gemm_bf16_kernel<<<grid1, 256>>>(ab, cmb, nullptr, nullptr, CSZ, 0, labels);

    // sim + tsim GEMMs in one launch (z selects student/teacher)
    dim3 grid2(BSZ / 128, BSZ / 128, 2);
    gemm_bf16_kernel<<<grid2, 256>>>(ab, ab, tb, tb, BSZ, 1, labels);

    rank_merge_kernel<<<BSZ, 128>>>();
    kd_kernel<<<BSZ, 256>>>(labels);
    final_kernel<<<1, 256>>>(epoch, out, out_size);
}

// round 17
// speedup vs baseline: 6.6508x; 1.0814x over previous
#include <cuda_runtime.h>
#include <cuda_bf16.h>
#include <cstdint>
#include <math.h>

#define BSZ 2048
#define ESZ 512
#define CSZ 16384
#define NBLK (CSZ / 128)
#define NSTAGE 3
#define NTILES (ESZ / 32)   // 16 K-tiles

// ---------------- scratch (static device globals; no allocation) ----------------
__device__ float g_sim[(size_t)BSZ * BSZ];      // 16 MiB
__device__ float g_tsim[(size_t)BSZ * BSZ];     // 16 MiB
__device__ float g_pmax[(size_t)BSZ * NBLK];
__device__ float g_psum[(size_t)BSZ * NBLK];
__device__ float g_rowlabel[BSZ];
__device__ float g_colscale[CSZ];
__device__ float g_rowrank[BSZ];
__device__ float g_rowkd[BSZ];
__device__ int   g_lab32[BSZ];
__device__ int   g_lab64;
__device__ __nv_bfloat16 g_cmb[(size_t)CSZ * ESZ];  // 16 MiB bf16 class_map
__device__ __nv_bfloat16 g_ab[(size_t)BSZ * ESZ];   // 2 MiB bf16 batch
__device__ __nv_bfloat16 g_tb[(size_t)BSZ * ESZ];   // 2 MiB bf16 teacher

// Detect labels dtype (int64 LE <256 -> all odd int32 words zero) and decode
// into g_lab32 once.
__global__ void detect_labels_kernel(const int* __restrict__ labels) {
    __shared__ int cnt[256];
    int t = threadIdx.x;
    int c = 0;
    for (int i = t; i < BSZ; i += 256)
        if ((i & 1) && labels[i] != 0) c++;
    cnt[t] = c;
    __syncthreads();
    for (int o = 128; o; o >>= 1) {
        if (t < o) cnt[t] += cnt[t + o];
        __syncthreads();
    }
    __syncthreads();
    int lab64 = (cnt[0] == 0) ? 1 : 0;
    if (t == 0) g_lab64 = lab64;
    for (int i = t; i < BSZ; i += 256)
        g_lab32[i] = lab64 ? labels[2 * i] : labels[i];
}

// fused fp32->bf16 conversion + (optional) row-norm scale. One warp per row.
// Each lane: 4 float4 loads (MLP 4), 2 uint4 stores, fp32 sumsq.
__global__ void cvt_norm_kernel(const float* __restrict__ src,
                                __nv_bfloat16* __restrict__ dst,
                                float* __restrict__ scale, int nrows) {
    int row = blockIdx.x * 8 + (threadIdx.x >> 5);
    int lane = threadIdx.x & 31;
    if (row >= nrows) return;
    const float4* s = (const float4*)(src + (size_t)row * ESZ);
    uint4* d = (uint4*)(dst + (size_t)row * ESZ);
    float ss = 0.f;
    #pragma unroll
    for (int i = 0; i < 2; i++) {
        float4 a = s[2 * lane + 64 * i];
        float4 b = s[2 * lane + 1 + 64 * i];
        ss += a.x*a.x + a.y*a.y + a.z*a.z + a.w*a.w
            + b.x*b.x + b.y*b.y + b.z*b.z + b.w*b.w;
        __nv_bfloat162 p0 = __floats2bfloat162_rn(a.x, a.y);
        __nv_bfloat162 p1 = __floats2bfloat162_rn(a.z, a.w);
        __nv_bfloat162 p2 = __floats2bfloat162_rn(b.x, b.y);
        __nv_bfloat162 p3 = __floats2bfloat162_rn(b.z, b.w);
        uint4 o;
        o.x = *(unsigned*)&p0; o.y = *(unsigned*)&p1;
        o.z = *(unsigned*)&p2; o.w = *(unsigned*)&p3;
        d[lane + 32 * i] = o;
    }
    #pragma unroll
    for (int o = 16; o; o >>= 1) ss += __shfl_xor_sync(0xffffffffu, ss, o);
    if (scale != nullptr && lane == 0) scale[row] = rsqrtf(ss) * 20.0f;  // /TEMP
}

// ---------------- asm helpers ----------------
__device__ __forceinline__ uint32_t smem_u32(const void* p) {
    uint32_t a;
    asm("{ .reg .u64 t; cvta.to.shared.u64 t, %1; cvt.u32.u64 %0, t; }"
        : "=r"(a) : "l"(p));
    return a;
}

__device__ __forceinline__ void cp_async16(uint32_t saddr, const void* gptr) {
    asm volatile("cp.async.cg.shared.global [%0], [%1], 16;"
                 :: "r"(saddr), "l"(gptr));
}
__device__ __forceinline__ void cp_commit() {
    asm volatile("cp.async.commit_group;");
}
template <int N>
__device__ __forceinline__ void cp_wait() {
    asm volatile("cp.async.wait_group %0;" :: "n"(N));
}

__device__ __forceinline__ void ldsm_x4(unsigned& r0, unsigned& r1,
                                        unsigned& r2, unsigned& r3, uint32_t addr) {
    asm volatile("ldmatrix.sync.aligned.m8n8.x4.shared.b16 {%0,%1,%2,%3}, [%4];"
                 : "=r"(r0), "=r"(r1), "=r"(r2), "=r"(r3) : "r"(addr));
}

__device__ __forceinline__ void mma_bf16(float* d, const unsigned* a, const unsigned* b) {
    asm volatile(
        "mma.sync.aligned.m16n8k16.row.col.f32.bf16.bf16.f32 "
        "{%0,%1,%2,%3}, {%4,%5,%6,%7}, {%8,%9}, {%0,%1,%2,%3};\n"
        : "+f"(d[0]), "+f"(d[1]), "+f"(d[2]), "+f"(d[3])
        : "r"(a[0]), "r"(a[1]), "r"(a[2]), "r"(a[3]), "r"(b[0]), "r"(b[1]));
}

// swizzled byte offset of 16B chunk (row, c) in a row-pitch-64B tile
__device__ __forceinline__ int tile_off(int row, int c) {
    return row * 64 + ((c ^ ((row >> 1) & 3)) << 4);
}

// ---------------- unified bf16 NT GEMM (proven R13 body, 1-D grid decode) ------
// bid [0,2048): logits tiles (dest 0): bn=(bid&127)*128, bm=(bid>>7)*128
// bid [2048,2304): sim  (dest 1); bid [2304,2560): tsim (dest 2)
__global__ void __launch_bounds__(256, 2) gemm_all_kernel(
    const __nv_bfloat16* __restrict__ ab, const __nv_bfloat16* __restrict__ cmb,
    const __nv_bfloat16* __restrict__ tb)
{
    __shared__ __align__(16) __nv_bfloat16 As[NSTAGE][128 * 32];
    __shared__ __align__(16) __nv_bfloat16 Bs[NSTAGE][128 * 32];

    int bid = blockIdx.x;
    int dest, bm, bn, cblk, N;
    const __nv_bfloat16 *A, *Bm;
    if (bid < 2048) {
        dest = 0; cblk = bid & 127;
        bn = cblk * 128; bm = (bid >> 7) * 128;
        A = ab; Bm = cmb; N = CSZ;
    } else {
        int r = bid - 2048;
        dest = 1 + (r >> 8);
        int r2 = r & 255;
        bn = (r2 & 15) * 128; bm = (r2 >> 4) * 128; cblk = 0;
        A = (dest == 2) ? tb : ab; Bm = A; N = BSZ;
    }

    int tid  = threadIdx.x;
    int lane = tid & 31;
    int wid  = tid >> 5;
    int warp_m = (wid >> 1) * 32;
    int wn_idx = wid & 1;
    int warp_n = wn_idx * 64;
    int lr = lane >> 2;
    int lc = lane & 3;

    uint32_t as_base = smem_u32(As);
    uint32_t bs_base = smem_u32(Bs);

    int rA    = (((lane >> 3) & 1) << 3) + (lane & 7);
    int cbitA = lane >> 4;
    int rB    = ((lane >> 4) << 3) + (lane & 7);
    int cbitB = (lane >> 3) & 1;

    int rowA[2], swA[2];
    #pragma unroll
    for (int mi = 0; mi < 2; mi++) {
        rowA[mi] = warp_m + mi * 16 + rA;
        swA[mi]  = (rowA[mi] >> 1) & 3;
    }
    int rowB[4], swB[4];
    #pragma unroll
    for (int nj = 0; nj < 4; nj++) {
        rowB[nj] = warp_n + nj * 16 + rB;
        swB[nj]  = (rowB[nj] >> 1) & 3;
    }

    int r0c = tid >> 2,         c0c = tid & 3;
    int r1c = (tid + 256) >> 2, c1c = tid & 3;
    const int ldg4 = ESZ >> 3;
    const uint4* Ap0 = (const uint4*)A + (size_t)(bm + r0c) * ldg4 + c0c;
    const uint4* Ap1 = (const uint4*)A + (size_t)(bm + r1c) * ldg4 + c1c;
    const uint4* Bp0 = (const uint4*)Bm + (size_t)(bn + r0c) * ldg4 + c0c;
    const uint4* Bp1 = (const uint4*)Bm + (size_t)(bn + r1c) * ldg4 + c1c;
    int sA0 = tile_off(r0c, c0c), sA1 = tile_off(r1c, c1c);

    float acc[2][8][4];
    #pragma unroll
    for (int mi = 0; mi < 2; mi++)
        #pragma unroll
        for (int ni = 0; ni < 8; ni++)
            #pragma unroll
            for (int j = 0; j < 4; j++) acc[mi][ni][j] = 0.f;

    #pragma unroll
    for (int s = 0; s < 2; s++) {
        uint32_t abuf = as_base + s * 8192;
        uint32_t bbuf = bs_base + s * 8192;
        cp_async16(abuf + sA0, Ap0 + s * 4);
        cp_async16(abuf + sA1, Ap1 + s * 4);
        cp_async16(bbuf + sA0, Bp0 + s * 4);
        cp_async16(bbuf + sA1, Bp1 + s * 4);
        cp_commit();
    }
    cp_wait<1>();
    __syncthreads();

    #pragma unroll
    for (int kt = 0; kt < NTILES; kt++) {
        int buf = kt % NSTAGE;
        uint32_t abuf = as_base + buf * 8192;
        uint32_t bbuf = bs_base + buf * 8192;
        #pragma unroll
        for (int ks = 0; ks < 2; ks++) {
            unsigned af[2][4], bfr[4][4];
            #pragma unroll
            for (int mi = 0; mi < 2; mi++) {
                int c = 2 * ks + cbitA;
                uint32_t ad = abuf + rowA[mi] * 64 + (((c ^ swA[mi]) & 3) << 4);
                ldsm_x4(af[mi][0], af[mi][1], af[mi][2], af[mi][3], ad);
            }
            #pragma unroll
            for (int nj = 0; nj < 4; nj++) {
                int c = 2 * ks + cbitB;
                uint32_t ad = bbuf + rowB[nj] * 64 + (((c ^ swB[nj]) & 3) << 4);
                ldsm_x4(bfr[nj][0], bfr[nj][1], bfr[nj][2], bfr[nj][3], ad);
            }
            #pragma unroll
            for (int mi = 0; mi < 2; mi++)
                #pragma unroll
                for (int ni = 0; ni < 8; ni++)
                    mma_bf16(acc[mi][ni], af[mi], &bfr[ni >> 1][(ni & 1) * 2]);
        }
        int nk = kt + 2;
        if (nk < NTILES) {
            int nb = nk % NSTAGE;
            uint32_t nab = as_base + nb * 8192;
            uint32_t nbb = bs_base + nb * 8192;
            cp_async16(nab + sA0, Ap0 + nk * 4);
            cp_async16(nab + sA1, Ap1 + nk * 4);
            cp_async16(nbb + sA0, Bp0 + nk * 4);
            cp_async16(nbb + sA1, Bp1 + nk * 4);
            cp_commit();
            cp_wait<1>();
        } else {
            cp_wait<0>();
        }
        __syncthreads();
    }

    if (dest == 0) {
        // pm/ps alias the (now dead) stage-0 smem
        float (*pm)[2] = (float(*)[2])&As[0][0];
        float (*ps)[2] = (float(*)[2])&As[0][512];
        float sc[8][2];
        #pragma unroll
        for (int ni = 0; ni < 8; ni++) {
            int n = bn + warp_n + ni * 8 + lc * 2;
            sc[ni][0] = g_colscale[n];
            sc[ni][1] = g_colscale[n + 1];
        }
        #pragma unroll
        for (int mi = 0; mi < 2; mi++) {
            #pragma unroll
            for (int h = 0; h < 2; h++) {
                int rloc = warp_m + mi * 16 + h * 8 + lr;
                int r = bm + rloc;
                int lab = g_lab32[r];
                float m = -1e30f;
                float vv[16];
                #pragma unroll
                for (int ni = 0; ni < 8; ni++) {
                    #pragma unroll
                    for (int j = 0; j < 2; j++) {
                        float v = acc[mi][ni][h * 2 + j] * sc[ni][j];
                        int col = bn + warp_n + ni * 8 + lc * 2 + j;
                        if (col == lab) g_rowlabel[r] = v;
                        vv[ni * 2 + j] = v;
                        m = fmaxf(m, v);
                    }
                }
                float s = 0.f;
                #pragma unroll
                for (int i = 0; i < 16; i++) s += __expf(vv[i] - m);
                #pragma unroll
                for (int o = 1; o <= 2; o <<= 1) {
                    float m2 = __shfl_xor_sync(0xffffffffu, m, o);
                    float s2 = __shfl_xor_sync(0xffffffffu, s, o);
                    float M = fmaxf(m, m2);
                    s = s * __expf(m - M) + s2 * __expf(m2 - M);
                    m = M;
                }
                if (lc == 0) {
                    pm[rloc][wn_idx] = m;
                    ps[rloc][wn_idx] = s;
                }
            }
        }
        __syncthreads();
        if (tid < 128) {
            float m0 = pm[tid][0], m1 = pm[tid][1];
            float M = fmaxf(m0, m1);
            float s = ps[tid][0] * __expf(m0 - M) + ps[tid][1] * __expf(m1 - M);
            g_pmax[(size_t)(bm + tid) * NBLK + cblk] = M;
            g_psum[(size_t)(bm + tid) * NBLK + cblk] = s;
        }
    } else {
        float* Cg = (dest == 2) ? g_tsim : g_sim;
        #pragma unroll
        for (int mi = 0; mi < 2; mi++) {
            #pragma unroll
            for (int h = 0; h < 2; h++) {
                int r = bm + warp_m + mi * 16 + h * 8 + lr;
                #pragma unroll
                for (int ni = 0; ni < 8; ni++) {
                    int n = bn + warp_n + ni * 8 + lc * 2;
                    float2 v;
                    v.x = acc[mi][ni][h * 2 + 0];
                    v.y = acc[mi][ni][h * 2 + 1];
                    *(float2*)(Cg + (size_t)r * N + n) = v;
                }
            }
        }
    }
}

// merge the NBLK logsumexp partials per row; subtract the label logit
__global__ void rank_merge_kernel() {
    int b = blockIdx.x;
    int t = threadIdx.x;
    __shared__ float sm[128], ss[128];
    sm[t] = g_pmax[(size_t)b * NBLK + t];
    ss[t] = g_psum[(size_t)b * NBLK + t];
    __syncthreads();
    for (int o = 64; o; o >>= 1) {
        if (t < o) {
            float m2 = sm[t + o], s2 = ss[t + o];
            float M = fmaxf(sm[t], m2);
            ss[t] = ss[t] * __expf(sm[t] - M) + s2 * __expf(m2 - M);
            sm[t] = M;
        }
        __syncthreads();
    }
    if (t == 0) g_rowrank[b] = sm[0] + logf(ss[0]) - g_rowlabel[b];
}

// one-pass per-row KD:
// kl = W/St - (lse_t - lse_s), W = sum exp(zt - mt) * (zt - zs)
__global__ void kd_kernel() {
    int b = blockIdx.x;
    int t = threadIdx.x;
    int lb = g_lab32[b];
    const float* srow = g_sim  + (size_t)b * BSZ;
    const float* trow = g_tsim + (size_t)b * BSZ;

    float ms = -1e30f, Ss = 0.f;
    float mt = -1e30f, St = 0.f, W = 0.f;
    for (int j = t; j < BSZ; j += 256) {
        float sc = (g_lab32[j] == lb) ? 0.25f : 0.125f;  // 1/TAU, BETA/TAU
        float a = srow[j] * sc;
        float c = trow[j] * sc;
        if (a > ms) { Ss = Ss * __expf(ms - a) + 1.f; ms = a; }
        else        { Ss += __expf(a - ms); }
        if (c > mt) {
            float e = __expf(mt - c);
            St = St * e + 1.f;
            W  = W * e + (c - a);
            mt = c;
        } else {
            float e = __expf(c - mt);
            St += e;
            W  += e * (c - a);
        }
    }
    __shared__ float rms[256], rSs[256], rmt[256], rSt[256], rW[256];
    rms[t] = ms; rSs[t] = Ss; rmt[t] = mt; rSt[t] = St; rW[t] = W;
    __syncthreads();
    for (int o = 128; o; o >>= 1) {
        if (t < o) {
            float m2 = rms[t + o], S2 = rSs[t + o];
            float M = fmaxf(rms[t], m2);
            rSs[t] = rSs[t] * __expf(rms[t] - M) + S2 * __expf(m2 - M);
            rms[t] = M;
            float mt2 = rmt[t + o], St2 = rSt[t + o], W2 = rW[t + o];
            float Mt = fmaxf(rmt[t], mt2);
            float e1 = __expf(rmt[t] - Mt), e2 = __expf(mt2 - Mt);
            rSt[t] = rSt[t] * e1 + St2 * e2;
            rW[t]  = rW[t]  * e1 + W2  * e2;
            rmt[t] = Mt;
        }
        __syncthreads();
    }
    if (t == 0) {
        float lse_s = rms[0] + logf(rSs[0]);
        float lse_t = rmt[0] + logf(rSt[0]);
        g_rowkd[b] = rW[0] / rSt[0] - (lse_t - lse_s);
    }
}

__global__ void final_kernel(const int* __restrict__ epoch_ptr, float* __restrict__ out,
                             int out_size) {
    __shared__ float r1[256], r2[256];
    int t = threadIdx.x;
    float a = 0.f, c = 0.f;
    for (int i = t; i < BSZ; i += 256) { a += g_rowrank[i]; c += g_rowkd[i]; }
    r1[t] = a; r2[t] = c;
    __syncthreads();
    for (int o = 128; o; o >>= 1) {
        if (t < o) { r1[t] += r1[t + o]; r2[t] += r2[t + o]; }
        __syncthreads();
    }
    if (t == 0) {
        float loss_rank = r1[0] * (1.0f / BSZ);
        float loss_kd   = r2[0] * (1.0f / BSZ);
        int epoch = epoch_ptr[0];
        float ramp = ((float)epoch / 150.0f) * 16.0f;  // (epoch/N_EPOCHS)*ALPHA*TAU^2
        float loss = loss_rank + ramp * loss_kd;
        out[0] = loss;
        if (out_size > 1) out[1] = loss_rank;
        if (out_size > 2) out[2] = loss_kd;
    }
}

extern "C" void kernel_launch(void* const* d_in, const int* in_sizes, int n_in,
                              void* d_out, int out_size) {
    const float* batch   = (const float*)d_in[0];
    const float* teacher = (const float*)d_in[1];
    const float* cm      = (const float*)d_in[2];
    const int*   labels  = (const int*)d_in[3];
    const int*   epoch   = (const int*)d_in[4];
    float* out = (float*)d_out;

    detect_labels_kernel<<<1, 256>>>(labels);

    __nv_bfloat16 *cmb, *ab, *tb;
    float* colscale;
    cudaGetSymbolAddress((void**)&cmb, g_cmb);
    cudaGetSymbolAddress((void**)&ab,  g_ab);
    cudaGetSymbolAddress((void**)&tb,  g_tb);
    cudaGetSymbolAddress((void**)&colscale, g_colscale);

    cvt_norm_kernel<<<CSZ / 8, 256>>>(cm, cmb, colscale, CSZ);
    cvt_norm_kernel<<<BSZ / 8, 256>>>(batch, ab, nullptr, BSZ);
    cvt_norm_kernel<<<BSZ / 8, 256>>>(teacher, tb, nullptr, BSZ);

    // all three GEMMs in one launch: 2048 logits + 256 sim + 256 tsim CTAs
    gemm_all_kernel<<<2560, 256>>>(ab, cmb, tb);

    rank_merge_kernel<<<BSZ, 128>>>();
    kd_kernel<<<BSZ, 256>>>();
    final_kernel<<<1, 256>>>(epoch, out, out_size);
}